// round 1
// baseline (speedup 1.0000x reference)
#include <cuda_runtime.h>
#include <cuda_bf16.h>
#include <cstdint>
#include <cstdio>

// Problem dims
#define NSEQ 4096
#define DIM  1024

// ---------------- scratch (static device allocations; no cudaMalloc) ----------------
__device__ float g_xt[NSEQ * DIM];                    // x rounded to tf32
__device__ float g_wt[3 * DIM * DIM];                 // wq,wk,wv rounded to tf32
__device__ float g_qkv[3 * NSEQ * DIM];               // Q,K,V (tf32-rounded values)
__device__ float g_vt[DIM * NSEQ];                    // V^T
__device__ float g_S[(size_t)NSEQ * NSEQ];            // scores (fp32)
__device__ float g_P[(size_t)NSEQ * NSEQ];            // softmax probs (tf32-rounded)

// ---------------- helpers ----------------
__device__ __forceinline__ float to_tf32(float x) {
    uint32_t u;
    asm volatile("cvt.rna.tf32.f32 %0, %1;" : "=r"(u) : "f"(x));
    return __uint_as_float(u);
}

__device__ __forceinline__ void ldsm_x4(uint32_t& r0, uint32_t& r1, uint32_t& r2, uint32_t& r3,
                                        uint32_t addr) {
    asm volatile("ldmatrix.sync.aligned.m8n8.x4.shared.b16 {%0,%1,%2,%3}, [%4];\n"
                 : "=r"(r0), "=r"(r1), "=r"(r2), "=r"(r3)
                 : "r"(addr));
}

__device__ __forceinline__ void mma_tf32(float c[4], uint32_t a0, uint32_t a1, uint32_t a2,
                                         uint32_t a3, uint32_t b0, uint32_t b1) {
    asm volatile(
        "mma.sync.aligned.m16n8k8.row.col.f32.tf32.tf32.f32 "
        "{%0,%1,%2,%3}, {%4,%5,%6,%7}, {%8,%9}, {%0,%1,%2,%3};\n"
        : "+f"(c[0]), "+f"(c[1]), "+f"(c[2]), "+f"(c[3])
        : "r"(a0), "r"(a1), "r"(a2), "r"(a3), "r"(b0), "r"(b1));
}

// ---------------- convert inputs: fp32 -> tf32-rounded fp32 ----------------
__global__ void convert_kernel(const float* __restrict__ x, const float* __restrict__ wq,
                               const float* __restrict__ wk, const float* __restrict__ wv) {
    const int stride = gridDim.x * blockDim.x;
    const int tid = blockIdx.x * blockDim.x + threadIdx.x;
    const int nx4 = (NSEQ * DIM) / 4;
    for (int i = tid; i < nx4; i += stride) {
        float4 f = ((const float4*)x)[i];
        ((float4*)g_xt)[i] = make_float4(to_tf32(f.x), to_tf32(f.y), to_tf32(f.z), to_tf32(f.w));
    }
    const int nw4 = (DIM * DIM) / 4;
    for (int i = tid; i < nw4; i += stride) {
        float4 a = ((const float4*)wq)[i];
        float4 b = ((const float4*)wk)[i];
        float4 c = ((const float4*)wv)[i];
        ((float4*)g_wt)[i]           = make_float4(to_tf32(a.x), to_tf32(a.y), to_tf32(a.z), to_tf32(a.w));
        ((float4*)g_wt)[nw4 + i]     = make_float4(to_tf32(b.x), to_tf32(b.y), to_tf32(b.z), to_tf32(b.w));
        ((float4*)g_wt)[2 * nw4 + i] = make_float4(to_tf32(c.x), to_tf32(c.y), to_tf32(c.z), to_tf32(c.w));
    }
}

// ---------------- GEMM: C[M,N] = A[M,K] * B[N,K]^T  (both operands k-contiguous) -------
// tf32 mma.sync m16n8k8, block tile 128x128x32, 8 warps (2x4), warp tile 64x32.
#define BM 128
#define BN 128
#define BK 32
#define LDS_PAD 4
#define LDS_W (BK + LDS_PAD)   // 36 floats = 144B row stride (conflict-free for ldmatrix)

__global__ __launch_bounds__(256)
void gemm_tt(const float* __restrict__ A, const float* __restrict__ B, float* __restrict__ C,
             int M, int N, int K, int round_out) {
    __shared__ float As[BM][LDS_W];
    __shared__ float Bs[BN][LDS_W];

    const int tid  = threadIdx.x;
    const int lane = tid & 31;
    const int warp = tid >> 5;
    const int wm = warp >> 2;   // 0..1 -> m offset wm*64
    const int wn = warp & 3;    // 0..3 -> n offset wn*32

    const int rm0 = blockIdx.y * BM;
    const int cn0 = blockIdx.x * BN;

    float c[4][4][4];
#pragma unroll
    for (int i = 0; i < 4; i++)
#pragma unroll
        for (int j = 0; j < 4; j++)
#pragma unroll
            for (int r = 0; r < 4; r++) c[i][j][r] = 0.f;

    for (int kt = 0; kt < K; kt += BK) {
        // cooperative load: 128 rows x 32 floats for A and B (8 float4 per thread)
#pragma unroll
        for (int s = 0; s < 4; s++) {
            int id = tid + s * 256;     // 0..1023
            int r = id >> 3;            // 0..127
            int q = id & 7;             // float4 index within row
            *(float4*)&As[r][q * 4] = *(const float4*)(A + (size_t)(rm0 + r) * K + kt + q * 4);
            *(float4*)&Bs[r][q * 4] = *(const float4*)(B + (size_t)(cn0 + r) * K + kt + q * 4);
        }
        __syncthreads();

#pragma unroll
        for (int kk = 0; kk < BK; kk += 8) {
            uint32_t a[4][4], b[4][2];
#pragma unroll
            for (int i = 0; i < 4; i++) {
                uint32_t addr = (uint32_t)__cvta_generic_to_shared(
                    &As[wm * 64 + i * 16 + (lane & 15)][kk + ((lane >> 4) << 2)]);
                ldsm_x4(a[i][0], a[i][1], a[i][2], a[i][3], addr);
            }
#pragma unroll
            for (int j0 = 0; j0 < 4; j0 += 2) {
                int pair = lane >> 3;   // ldmatrix matrix index
                uint32_t addr = (uint32_t)__cvta_generic_to_shared(
                    &Bs[wn * 32 + (j0 + (pair >> 1)) * 8 + (lane & 7)][kk + ((pair & 1) << 2)]);
                uint32_t r0, r1, r2, r3;
                ldsm_x4(r0, r1, r2, r3, addr);
                b[j0][0] = r0; b[j0][1] = r1; b[j0 + 1][0] = r2; b[j0 + 1][1] = r3;
            }
#pragma unroll
            for (int i = 0; i < 4; i++)
#pragma unroll
                for (int j = 0; j < 4; j++)
                    mma_tf32(c[i][j], a[i][0], a[i][1], a[i][2], a[i][3], b[j][0], b[j][1]);
        }
        __syncthreads();
    }

    // epilogue
    const int tr = lane >> 2;
    const int tc = (lane & 3) * 2;
#pragma unroll
    for (int i = 0; i < 4; i++) {
#pragma unroll
        for (int j = 0; j < 4; j++) {
            size_t row = (size_t)(rm0 + wm * 64 + i * 16 + tr);
            int col = cn0 + wn * 32 + j * 8 + tc;
            float v0 = c[i][j][0], v1 = c[i][j][1], v2 = c[i][j][2], v3 = c[i][j][3];
            if (round_out) { v0 = to_tf32(v0); v1 = to_tf32(v1); v2 = to_tf32(v2); v3 = to_tf32(v3); }
            *(float2*)&C[row * N + col]       = make_float2(v0, v1);
            *(float2*)&C[(row + 8) * N + col] = make_float2(v2, v3);
        }
    }
}

// ---------------- transpose V [rows x cols] -> Vt [cols x rows] ----------------
__global__ void transpose_kernel(const float* __restrict__ in, float* __restrict__ out,
                                 int rows, int cols) {
    __shared__ float tile[32][33];
    int cbase = blockIdx.x * 32;
    int rbase = blockIdx.y * 32;
    int tx = threadIdx.x, ty = threadIdx.y;
#pragma unroll
    for (int j = 0; j < 32; j += 8)
        tile[ty + j][tx] = in[(size_t)(rbase + ty + j) * cols + cbase + tx];
    __syncthreads();
#pragma unroll
    for (int j = 0; j < 32; j += 8)
        out[(size_t)(cbase + ty + j) * rows + rbase + tx] = tile[tx][ty + j];
}

// ---------------- row softmax: P = softmax(S * 1/32), output tf32-rounded ----------------
__global__ __launch_bounds__(256)
void softmax_kernel(const float* __restrict__ S, float* __restrict__ P) {
    const int row = blockIdx.x;
    const float scale = 0.03125f;   // 1/sqrt(1024)
    const float* s = S + (size_t)row * NSEQ;
    float* p = P + (size_t)row * NSEQ;
    const int tid = threadIdx.x;
    const int lane = tid & 31, warp = tid >> 5;
    __shared__ float sh[8];

    float v[16];
    float mx = -1e30f;
#pragma unroll
    for (int t = 0; t < 16; t++) {
        v[t] = s[tid + t * 256] * scale;
        mx = fmaxf(mx, v[t]);
    }
#pragma unroll
    for (int o = 16; o; o >>= 1) mx = fmaxf(mx, __shfl_xor_sync(0xffffffffu, mx, o));
    if (lane == 0) sh[warp] = mx;
    __syncthreads();
    if (tid == 0) {
        float t = sh[0];
#pragma unroll
        for (int i = 1; i < 8; i++) t = fmaxf(t, sh[i]);
        sh[0] = t;
    }
    __syncthreads();
    mx = sh[0];
    __syncthreads();

    float sum = 0.f;
#pragma unroll
    for (int t = 0; t < 16; t++) {
        v[t] = __expf(v[t] - mx);
        sum += v[t];
    }
#pragma unroll
    for (int o = 16; o; o >>= 1) sum += __shfl_xor_sync(0xffffffffu, sum, o);
    if (lane == 0) sh[warp] = sum;
    __syncthreads();
    if (tid == 0) {
        float t = 0.f;
#pragma unroll
        for (int i = 0; i < 8; i++) t += sh[i];
        sh[0] = t;
    }
    __syncthreads();
    const float inv = 1.0f / sh[0];
#pragma unroll
    for (int t = 0; t < 16; t++) p[tid + t * 256] = to_tf32(v[t] * inv);
}

// ---------------- launch ----------------
extern "C" void kernel_launch(void* const* d_in, const int* in_sizes, int n_in,
                              void* d_out, int out_size) {
    const float* x  = (const float*)d_in[0];
    const float* wq = (const float*)d_in[1];
    const float* wk = (const float*)d_in[2];
    const float* wv = (const float*)d_in[3];
    float* out = (float*)d_out;

    float *p_xt, *p_wt, *p_qkv, *p_vt, *p_S, *p_P;
    cudaGetSymbolAddress((void**)&p_xt, g_xt);
    cudaGetSymbolAddress((void**)&p_wt, g_wt);
    cudaGetSymbolAddress((void**)&p_qkv, g_qkv);
    cudaGetSymbolAddress((void**)&p_vt, g_vt);
    cudaGetSymbolAddress((void**)&p_S, g_S);
    cudaGetSymbolAddress((void**)&p_P, g_P);

    // 1) round inputs to tf32
    convert_kernel<<<2048, 256>>>(x, wq, wk, wv);

    // 2) Q, K, V = x @ w^T  (M=4096, N=1024, K=1024), tf32-rounded outputs
    dim3 gqkv(DIM / BN, NSEQ / BM);
    for (int i = 0; i < 3; i++) {
        gemm_tt<<<gqkv, 256>>>(p_xt, p_wt + (size_t)i * DIM * DIM,
                               p_qkv + (size_t)i * NSEQ * DIM, NSEQ, DIM, DIM, 1);
    }

    // 3) V^T for the P@V GEMM
    transpose_kernel<<<dim3(DIM / 32, NSEQ / 32), dim3(32, 8)>>>(
        p_qkv + (size_t)2 * NSEQ * DIM, p_vt, NSEQ, DIM);

    // 4) S = Q @ K^T  (M=N=4096, K=1024), fp32 output
    gemm_tt<<<dim3(NSEQ / BN, NSEQ / BM), 256>>>(p_qkv, p_qkv + (size_t)NSEQ * DIM, p_S,
                                                 NSEQ, NSEQ, DIM, 0);

    // 5) P = softmax(S / 32), tf32-rounded
    softmax_kernel<<<NSEQ, 256>>>(p_S, p_P);

    // 6) out = P @ V  == P @ (V^T)^T  (M=4096, N=1024, K=4096), fp32 output
    gemm_tt<<<dim3(DIM / BN, NSEQ / BM), 256>>>(p_P, p_vt, out, NSEQ, DIM, NSEQ, 0);
}